// round 1
// baseline (speedup 1.0000x reference)
#include <cuda_runtime.h>
#include <math.h>

// Problem constants (fixed by the dataset problem)
#define NEXP   16
#define DIM    1024
#define FDIM   4096
#define SHDIM  2048
#define MAXT   8192
#define NSORT  8192      // next pow2 >= T
#define MAXCAP 1024

// ---------------- scratch (static __device__ globals; no allocations) -------
__device__ float g_scoresT[NEXP * MAXT];                         // [E][T]
__device__ int   g_ids[NEXP * MAXCAP];                           // [E][cap]
__device__ float g_tscore[NEXP * MAXCAP];                        // [E][cap]
__device__ float g_act[(size_t)NEXP * MAXCAP * FDIM];            // 256 MB
__device__ float g_shact[(size_t)MAXT * SHDIM];                  // 64 MB

__device__ __forceinline__ float sigmoidf_(float x) { return 1.f / (1.f + expf(-x)); }
__device__ __forceinline__ float siluf_(float x)    { return x   / (1.f + expf(-x)); }

// ---------------- gate: scores[e][t] = sigmoid(h[t] . gate_w[e]) ------------
__global__ void gate_kernel(const float* __restrict__ h,
                            const float* __restrict__ gate_w,
                            float* __restrict__ scoresT, int T) {
    int warp = (int)((blockIdx.x * blockDim.x + threadIdx.x) >> 5);
    int lane = threadIdx.x & 31;
    if (warp >= T) return;
    const float* hr = h + (size_t)warp * DIM;
    float hreg[32];
#pragma unroll
    for (int i = 0; i < 32; i++) hreg[i] = hr[lane + 32 * i];
#pragma unroll
    for (int e = 0; e < NEXP; e++) {
        const float* w = gate_w + e * DIM;
        float s = 0.f;
#pragma unroll
        for (int i = 0; i < 32; i++) s = fmaf(hreg[i], w[lane + 32 * i], s);
#pragma unroll
        for (int o = 16; o; o >>= 1) s += __shfl_xor_sync(0xffffffffu, s, o);
        if (lane == 0) scoresT[e * T + warp] = sigmoidf_(s);
    }
}

// ---------------- top-k per expert: exact, stable like jax.lax.top_k --------
// 64-bit key: (ordered score bits << 32) | (0xFFFFFFFF - idx); descending sort
// gives score-desc, idx-asc tie-break — identical selection to top_k.
__global__ void topk_kernel(const float* __restrict__ scoresT,
                            int* __restrict__ ids, float* __restrict__ tscore,
                            int T, int cap) {
    extern __shared__ unsigned long long s_keys[];
    int e = blockIdx.x;
    const float* s = scoresT + (size_t)e * T;
    for (int i = threadIdx.x; i < NSORT; i += blockDim.x) {
        float v = (i < T) ? s[i] : -1e30f;
        unsigned u  = __float_as_uint(v);
        unsigned ob = (u & 0x80000000u) ? ~u : (u | 0x80000000u);
        s_keys[i] = ((unsigned long long)ob << 32) | (unsigned)(0xFFFFFFFFu - (unsigned)i);
    }
    __syncthreads();
    for (unsigned k = 2; k <= NSORT; k <<= 1) {
        for (unsigned j = k >> 1; j > 0; j >>= 1) {
            for (unsigned i = threadIdx.x; i < NSORT; i += blockDim.x) {
                unsigned ixj = i ^ j;
                if (ixj > i) {
                    unsigned long long a = s_keys[i], b = s_keys[ixj];
                    bool up = ((i & k) == 0);
                    bool sw = up ? (a < b) : (a > b);   // descending overall
                    if (sw) { s_keys[i] = b; s_keys[ixj] = a; }
                }
            }
            __syncthreads();
        }
    }
    for (int i = threadIdx.x; i < cap; i += blockDim.x) {
        unsigned idx = 0xFFFFFFFFu - (unsigned)(s_keys[i] & 0xFFFFFFFFull);
        ids[e * cap + i]    = (int)idx;
        tscore[e * cap + i] = s[idx];
    }
}

// ---------------- generic NT GEMM: C[m,n] = sum_k A[m,k]*B[n,k] -------------
// 128x128 tile, BK=16, 256 threads, 8x8 microtile, double-buffered smem.
// EPI: 0 = silu(acc+bias) store        (expert gate / shared gate)
//      1 = (acc+bias) * C_old store    (expert up / shared up, GLU multiply)
//      2 = atomicAdd(out[tok], (acc+bias)*rowScale)   (expert down + combine)
//      3 = plain store                  (shared down)
struct GemmArgs {
    const float* A; long long aStride; int lda;
    const float* B; long long bStride;                 // ldb == K
    float* C;       long long cStride; int ldc;
    const float* bias; long long biasStride;
    const int*   gatherA;                              // per-batch stride = M
    const float* rowScale;                             // per-batch stride = M
    const int*   scatterRows;                          // per-batch stride = M
    float* scatterOut; int scatterLd;
    int M, N, K;
};

template <int EPI>
__global__ __launch_bounds__(256, 2)
void gemm_nt(GemmArgs p) {
    __shared__ float As[2][16][132];
    __shared__ float Bs[2][16][132];
    __shared__ int   rowIds[128];

    const int b = blockIdx.z;
    const float* A    = p.A + (long long)b * p.aStride;
    const float* B    = p.B + (long long)b * p.bStride;
    float* C          = p.C ? p.C + (long long)b * p.cStride : nullptr;
    const float* bias = p.bias ? p.bias + (long long)b * p.biasStride : nullptr;
    const int*   gA   = p.gatherA ? p.gatherA + (long long)b * p.M : nullptr;
    const float* rsc  = p.rowScale ? p.rowScale + (long long)b * p.M : nullptr;
    const int*   srow = p.scatterRows ? p.scatterRows + (long long)b * p.M : nullptr;

    const int m0 = blockIdx.y * 128;
    const int n0 = blockIdx.x * 128;
    const int tid = threadIdx.x;

    if (tid < 128) rowIds[tid] = gA ? gA[m0 + tid] : (m0 + tid);
    __syncthreads();

    const int lr = tid >> 2;            // 0..63
    const int lc = (tid & 3) << 2;      // 0,4,8,12
    const int K  = p.K;
    const int ntiles = K >> 4;

    const float* Ar0 = A + (long long)rowIds[lr]      * p.lda + lc;
    const float* Ar1 = A + (long long)rowIds[lr + 64] * p.lda + lc;
    const float* Br0 = B + (long long)(n0 + lr)       * K     + lc;
    const float* Br1 = B + (long long)(n0 + lr + 64)  * K     + lc;

    float4 ra0 = *(const float4*)(Ar0);
    float4 ra1 = *(const float4*)(Ar1);
    float4 rb0 = *(const float4*)(Br0);
    float4 rb1 = *(const float4*)(Br1);

    float acc[8][8];
#pragma unroll
    for (int i = 0; i < 8; i++)
#pragma unroll
        for (int j = 0; j < 8; j++) acc[i][j] = 0.f;

    // stage tile 0
    As[0][lc + 0][lr] = ra0.x; As[0][lc + 1][lr] = ra0.y;
    As[0][lc + 2][lr] = ra0.z; As[0][lc + 3][lr] = ra0.w;
    As[0][lc + 0][lr + 64] = ra1.x; As[0][lc + 1][lr + 64] = ra1.y;
    As[0][lc + 2][lr + 64] = ra1.z; As[0][lc + 3][lr + 64] = ra1.w;
    Bs[0][lc + 0][lr] = rb0.x; Bs[0][lc + 1][lr] = rb0.y;
    Bs[0][lc + 2][lr] = rb0.z; Bs[0][lc + 3][lr] = rb0.w;
    Bs[0][lc + 0][lr + 64] = rb1.x; Bs[0][lc + 1][lr + 64] = rb1.y;
    Bs[0][lc + 2][lr + 64] = rb1.z; Bs[0][lc + 3][lr + 64] = rb1.w;
    __syncthreads();

    const int ty4 = (tid >> 4) << 2;
    const int tx4 = (tid & 15) << 2;

    for (int kt = 0; kt < ntiles; kt++) {
        const int buf = kt & 1;
        if (kt + 1 < ntiles) {
            const int ko = (kt + 1) << 4;
            ra0 = *(const float4*)(Ar0 + ko);
            ra1 = *(const float4*)(Ar1 + ko);
            rb0 = *(const float4*)(Br0 + ko);
            rb1 = *(const float4*)(Br1 + ko);
        }
#pragma unroll
        for (int kk = 0; kk < 16; kk++) {
            float4 a0 = *(const float4*)&As[buf][kk][ty4];
            float4 a1 = *(const float4*)&As[buf][kk][64 + ty4];
            float4 b0 = *(const float4*)&Bs[buf][kk][tx4];
            float4 b1 = *(const float4*)&Bs[buf][kk][64 + tx4];
            float av[8] = {a0.x, a0.y, a0.z, a0.w, a1.x, a1.y, a1.z, a1.w};
            float bv[8] = {b0.x, b0.y, b0.z, b0.w, b1.x, b1.y, b1.z, b1.w};
#pragma unroll
            for (int i = 0; i < 8; i++)
#pragma unroll
                for (int j = 0; j < 8; j++)
                    acc[i][j] = fmaf(av[i], bv[j], acc[i][j]);
        }
        if (kt + 1 < ntiles) {
            const int nb = (kt + 1) & 1;
            As[nb][lc + 0][lr] = ra0.x; As[nb][lc + 1][lr] = ra0.y;
            As[nb][lc + 2][lr] = ra0.z; As[nb][lc + 3][lr] = ra0.w;
            As[nb][lc + 0][lr + 64] = ra1.x; As[nb][lc + 1][lr + 64] = ra1.y;
            As[nb][lc + 2][lr + 64] = ra1.z; As[nb][lc + 3][lr + 64] = ra1.w;
            Bs[nb][lc + 0][lr] = rb0.x; Bs[nb][lc + 1][lr] = rb0.y;
            Bs[nb][lc + 2][lr] = rb0.z; Bs[nb][lc + 3][lr] = rb0.w;
            Bs[nb][lc + 0][lr + 64] = rb1.x; Bs[nb][lc + 1][lr + 64] = rb1.y;
            Bs[nb][lc + 2][lr + 64] = rb1.z; Bs[nb][lc + 3][lr + 64] = rb1.w;
        }
        __syncthreads();
    }

    // epilogue
    float bn[8];
#pragma unroll
    for (int j = 0; j < 8; j++) {
        int n = n0 + ((j < 4) ? (tx4 + j) : (64 + tx4 + j - 4));
        bn[j] = bias ? bias[n] : 0.f;
    }

#pragma unroll
    for (int i = 0; i < 8; i++) {
        int m = m0 + ((i < 4) ? (ty4 + i) : (64 + ty4 + i - 4));
        if (EPI == 2) {
            int   tok = srow[m];
            float sc  = rsc[m];
            float* orow = p.scatterOut + (long long)tok * p.scatterLd + n0;
#pragma unroll
            for (int j = 0; j < 8; j++) {
                int nn = (j < 4) ? (tx4 + j) : (64 + tx4 + j - 4);
                atomicAdd(orow + nn, (acc[i][j] + bn[j]) * sc);
            }
        } else {
            float* crow = C + (long long)m * p.ldc + n0;
            float t0[4], t1[4];
#pragma unroll
            for (int j = 0; j < 4; j++) {
                t0[j] = acc[i][j]     + bn[j];
                t1[j] = acc[i][j + 4] + bn[j + 4];
            }
            if (EPI == 0) {
#pragma unroll
                for (int j = 0; j < 4; j++) { t0[j] = siluf_(t0[j]); t1[j] = siluf_(t1[j]); }
            } else if (EPI == 1) {
                float4 o0 = *(const float4*)(crow + tx4);
                float4 o1 = *(const float4*)(crow + 64 + tx4);
                t0[0] *= o0.x; t0[1] *= o0.y; t0[2] *= o0.z; t0[3] *= o0.w;
                t1[0] *= o1.x; t1[1] *= o1.y; t1[2] *= o1.z; t1[3] *= o1.w;
            }
            *(float4*)(crow + tx4)      = make_float4(t0[0], t0[1], t0[2], t0[3]);
            *(float4*)(crow + 64 + tx4) = make_float4(t1[0], t1[1], t1[2], t1[3]);
        }
    }
}

// ---------------- launch ----------------------------------------------------
extern "C" void kernel_launch(void* const* d_in, const int* in_sizes, int n_in,
                              void* d_out, int out_size) {
    const float* x      = (const float*)d_in[0];
    const float* gate_w = (const float*)d_in[1];
    const float* up_w   = (const float*)d_in[2];
    const float* up_b   = (const float*)d_in[3];
    const float* gw     = (const float*)d_in[4];
    const float* gb     = (const float*)d_in[5];
    const float* down_w = (const float*)d_in[6];
    const float* down_b = (const float*)d_in[7];
    const float* shg    = (const float*)d_in[8];
    const float* shu    = (const float*)d_in[9];
    (void)n_in; (void)out_size;
    const float* shd    = (const float*)d_in[10];
    float* out = (float*)d_out;

    int T   = in_sizes[0] / DIM;                 // 8192
    int cap = (T * 2 + NEXP - 1) / NEXP;         // 1024

    float *scoresT, *tscore, *act, *shact; int* ids;
    cudaGetSymbolAddress((void**)&scoresT, g_scoresT);
    cudaGetSymbolAddress((void**)&ids,     g_ids);
    cudaGetSymbolAddress((void**)&tscore,  g_tscore);
    cudaGetSymbolAddress((void**)&act,     g_act);
    cudaGetSymbolAddress((void**)&shact,   g_shact);

    // 1) gate scores (transposed layout for top-k)
    gate_kernel<<<(T + 7) / 8, 256>>>(x, gate_w, scoresT, T);

    // 2) exact per-expert top-cap selection
    cudaFuncSetAttribute(topk_kernel, cudaFuncAttributeMaxDynamicSharedMemorySize,
                         NSORT * (int)sizeof(unsigned long long));
    topk_kernel<<<NEXP, 1024, NSORT * (int)sizeof(unsigned long long)>>>(
        scoresT, ids, tscore, T, cap);

    // 3) shared GLU MLP (writes `out` with plain stores — initializes it)
    GemmArgs s1{};
    s1.A = x;     s1.aStride = 0; s1.lda = DIM;
    s1.B = shg;   s1.bStride = 0;
    s1.C = shact; s1.cStride = 0; s1.ldc = SHDIM;
    s1.M = T; s1.N = SHDIM; s1.K = DIM;
    gemm_nt<0><<<dim3(SHDIM / 128, T / 128, 1), 256>>>(s1);

    GemmArgs s2 = s1; s2.B = shu;
    gemm_nt<1><<<dim3(SHDIM / 128, T / 128, 1), 256>>>(s2);

    GemmArgs s3{};
    s3.A = shact; s3.aStride = 0; s3.lda = SHDIM;
    s3.B = shd;   s3.bStride = 0;
    s3.C = out;   s3.cStride = 0; s3.ldc = DIM;
    s3.M = T; s3.N = DIM; s3.K = SHDIM;
    gemm_nt<3><<<dim3(DIM / 128, T / 128, 1), 256>>>(s3);

    // 4) expert GLU: gate -> silu (EPI0), up * silu(gate) (EPI1)
    GemmArgs e1{};
    e1.A = x;   e1.aStride = 0; e1.lda = DIM;
    e1.B = gw;  e1.bStride = (long long)FDIM * DIM;
    e1.C = act; e1.cStride = (long long)cap * FDIM; e1.ldc = FDIM;
    e1.bias = gb; e1.biasStride = FDIM;
    e1.gatherA = ids;
    e1.M = cap; e1.N = FDIM; e1.K = DIM;
    gemm_nt<0><<<dim3(FDIM / 128, cap / 128, NEXP), 256>>>(e1);

    GemmArgs e2 = e1; e2.B = up_w; e2.bias = up_b;
    gemm_nt<1><<<dim3(FDIM / 128, cap / 128, NEXP), 256>>>(e2);

    // 5) expert down + weighted scatter-add combine (after shared wrote `out`)
    GemmArgs e3{};
    e3.A = act;    e3.aStride = (long long)cap * FDIM; e3.lda = FDIM;
    e3.B = down_w; e3.bStride = (long long)DIM * FDIM;
    e3.C = nullptr; e3.cStride = 0; e3.ldc = 0;
    e3.bias = down_b; e3.biasStride = DIM;
    e3.scatterRows = ids; e3.rowScale = tscore;
    e3.scatterOut = out;  e3.scatterLd = DIM;
    e3.M = cap; e3.N = DIM; e3.K = FDIM;
    gemm_nt<2><<<dim3(DIM / 128, cap / 128, NEXP), 256>>>(e3);
}